// round 2
// baseline (speedup 1.0000x reference)
#include <cuda_runtime.h>
#include <cuda_bf16.h>

// BoxFilter: out[b,c,i,j] = sum of x over rows [max(0,i-R), min(H-1,i+R)]
//                                        cols [max(0,j-R), min(W-1,j+R)]
// (identity of diff_y(cumsum(diff_x(cumsum(x,H),r),W),r) with truncated edges)

#define R 4
#define NT 128                 // threads per block
#define CPT 4                  // columns per thread (float4)
#define TW (NT * CPT)          // 512 columns per block tile
#define RDEPTH 10              // vertical ring depth (2R+1 live rows + slack)
#define ZCHUNKS 9              // H split for parallelism / load balance

__device__ __forceinline__ float4 hbox_fast(const float* __restrict__ rowp, int c) {
    // cols c-4 .. c+7, all in-range, 16B aligned (c % 4 == 0)
    const float4* p = reinterpret_cast<const float4*>(rowp + (c - R));
    float4 a = p[0], b = p[1], d = p[2];
    float h0 = ((a.x + a.y) + (a.z + a.w)) + ((b.x + b.y) + (b.z + b.w)) + d.x;
    float h1 = h0 - a.x + d.y;
    float h2 = h1 - a.y + d.z;
    float h3 = h2 - a.z + d.w;
    return make_float4(h0, h1, h2, h3);
}

__device__ __forceinline__ float4 hbox_slow(const float* __restrict__ rowp, int c, int W) {
    float s[2 * R + CPT];
#pragma unroll
    for (int k = 0; k < 2 * R + CPT; ++k) {
        int cc = c - R + k;
        s[k] = (cc >= 0 && cc < W) ? rowp[cc] : 0.0f;
    }
    float h0 = 0.0f;
#pragma unroll
    for (int k = 0; k < 2 * R + 1; ++k) h0 += s[k];
    float h1 = h0 - s[0] + s[2 * R + 1];
    float h2 = h1 - s[1] + s[2 * R + 2];
    float h3 = h2 - s[2] + s[2 * R + 3];
    return make_float4(h0, h1, h2, h3);
}

__global__ __launch_bounds__(NT) void box_kernel(
    const float* __restrict__ x, float* __restrict__ out,
    int H, int W, int rows_per_chunk)
{
    __shared__ float4 ring[RDEPTH][NT];

    const int t = threadIdx.x;
    const int c = blockIdx.x * TW + t * CPT;
    const bool active = (c < W);
    const bool fast = (c >= R) && (c + CPT - 1 + R < W);

    const size_t img_off = (size_t)blockIdx.y * (size_t)H * (size_t)W;
    const float* img = x + img_off;
    float* oimg = out + img_off;

    const int y0 = blockIdx.z * rows_per_chunk;
    if (y0 >= H) return;
    const int y1 = min(H, y0 + rows_per_chunk);

    float4 vsum = make_float4(0.0f, 0.0f, 0.0f, 0.0f);

    const int rstart = max(0, y0 - R);
    int addslot = rstart % RDEPTH;
    int subslot = addslot;

    // Prime: rows [rstart, y0+R) clamped to H
    for (int row = rstart; row < y0 + R && row < H; ++row) {
        float4 h = make_float4(0.0f, 0.0f, 0.0f, 0.0f);
        if (active) {
            const float* rowp = img + (size_t)row * W;
            h = fast ? hbox_fast(rowp, c) : hbox_slow(rowp, c, W);
        }
        ring[addslot][t] = h;
        vsum.x += h.x; vsum.y += h.y; vsum.z += h.z; vsum.w += h.w;
        if (++addslot == RDEPTH) addslot = 0;
    }

    // Split sweep: head (i-R may be <0), body (both in-range), tail (i+R may be >=H)
    const int body_lo = min(y1, max(y0, R));           // first i with i-R >= 0
    const int body_hi = max(body_lo, min(y1, H - R));  // last+1 i with i+R < H

    // --- head ---
    for (int i = y0; i < body_lo; ++i) {
        const int ra = i + R;
        if (ra < H) {
            float4 h = make_float4(0.0f, 0.0f, 0.0f, 0.0f);
            if (active) {
                const float* rowp = img + (size_t)ra * W;
                h = fast ? hbox_fast(rowp, c) : hbox_slow(rowp, c, W);
            }
            ring[addslot][t] = h;
            vsum.x += h.x; vsum.y += h.y; vsum.z += h.z; vsum.w += h.w;
            if (++addslot == RDEPTH) addslot = 0;
        }
        if (active) *reinterpret_cast<float4*>(oimg + (size_t)i * W + c) = vsum;
        // i - R < 0: no subtract in head
    }

    // --- body: fully interior, branch-free, unrolled x2 ---
    if (active && fast) {
        int i = body_lo;
        for (; i + 1 < body_hi; i += 2) {
#pragma unroll
            for (int u = 0; u < 2; ++u) {
                const int ii = i + u;
                const float* rowp = img + (size_t)(ii + R) * W;
                float4 h = hbox_fast(rowp, c);
                ring[addslot][t] = h;
                vsum.x += h.x; vsum.y += h.y; vsum.z += h.z; vsum.w += h.w;
                if (++addslot == RDEPTH) addslot = 0;
                *reinterpret_cast<float4*>(oimg + (size_t)ii * W + c) = vsum;
                float4 g = ring[subslot][t];
                vsum.x -= g.x; vsum.y -= g.y; vsum.z -= g.z; vsum.w -= g.w;
                if (++subslot == RDEPTH) subslot = 0;
            }
        }
        for (; i < body_hi; ++i) {
            const float* rowp = img + (size_t)(i + R) * W;
            float4 h = hbox_fast(rowp, c);
            ring[addslot][t] = h;
            vsum.x += h.x; vsum.y += h.y; vsum.z += h.z; vsum.w += h.w;
            if (++addslot == RDEPTH) addslot = 0;
            *reinterpret_cast<float4*>(oimg + (size_t)i * W + c) = vsum;
            float4 g = ring[subslot][t];
            vsum.x -= g.x; vsum.y -= g.y; vsum.z -= g.z; vsum.w -= g.w;
            if (++subslot == RDEPTH) subslot = 0;
        }
    } else {
        for (int i = body_lo; i < body_hi; ++i) {
            float4 h = make_float4(0.0f, 0.0f, 0.0f, 0.0f);
            if (active) {
                const float* rowp = img + (size_t)(i + R) * W;
                h = fast ? hbox_fast(rowp, c) : hbox_slow(rowp, c, W);
            }
            ring[addslot][t] = h;
            vsum.x += h.x; vsum.y += h.y; vsum.z += h.z; vsum.w += h.w;
            if (++addslot == RDEPTH) addslot = 0;
            if (active) *reinterpret_cast<float4*>(oimg + (size_t)i * W + c) = vsum;
            float4 g = ring[subslot][t];
            vsum.x -= g.x; vsum.y -= g.y; vsum.z -= g.z; vsum.w -= g.w;
            if (++subslot == RDEPTH) subslot = 0;
        }
    }

    // --- tail: i + R may exceed H-1 ---
    for (int i = body_hi; i < y1; ++i) {
        const int ra = i + R;
        if (ra < H) {
            float4 h = make_float4(0.0f, 0.0f, 0.0f, 0.0f);
            if (active) {
                const float* rowp = img + (size_t)ra * W;
                h = fast ? hbox_fast(rowp, c) : hbox_slow(rowp, c, W);
            }
            ring[addslot][t] = h;
            vsum.x += h.x; vsum.y += h.y; vsum.z += h.z; vsum.w += h.w;
            if (++addslot == RDEPTH) addslot = 0;
        }
        if (active) *reinterpret_cast<float4*>(oimg + (size_t)i * W + c) = vsum;
        if (i - R >= 0) {
            float4 g = ring[subslot][t];
            vsum.x -= g.x; vsum.y -= g.y; vsum.z -= g.z; vsum.w -= g.w;
            if (++subslot == RDEPTH) subslot = 0;
        }
    }
}

extern "C" void kernel_launch(void* const* d_in, const int* in_sizes, int n_in,
                              void* d_out, int out_size) {
    const float* x = (const float*)d_in[0];
    float* out = (float*)d_out;

    const int H = 1080;
    const int W = 1920;
    const int BC = out_size / (H * W);   // 24 (B*C)

    const int rows_per_chunk = (H + ZCHUNKS - 1) / ZCHUNKS;  // 120
    dim3 grid((W + TW - 1) / TW, BC, ZCHUNKS);               // 4 x 24 x 9 = 864 blocks
    box_kernel<<<grid, NT>>>(x, out, H, W, rows_per_chunk);
}

// round 6
// speedup vs baseline: 1.0971x; 1.0971x over previous
#include <cuda_runtime.h>
#include <cuda_bf16.h>

// BoxFilter: out[b,c,i,j] = sum of x over rows [max(0,i-R), min(H-1,i+R)]
//                                        cols [max(0,j-R), min(W-1,j+R)]
// (identity of diff_y(cumsum(diff_x(cumsum(x,H),r),W),r) with truncated edges)
//
// No smem, no syncs. Vertical running sum; the subtract side re-reads row i-R
// (L2/L1-hot, read 9 rows earlier) instead of keeping a shared-memory ring.

#define R 4
#define NT 160                 // threads per block (5 warps)
#define MINB 8                 // min blocks/SM -> regs capped at 51, 40 warps/SM
#define CPT 4                  // columns per thread (float4)
#define TW (NT * CPT)          // 640 columns per block tile -> 1920/640 = 3 exact
#define ZCHUNKS 24             // 1080/24 = 45-row chunks -> 1728 blocks

__device__ __forceinline__ float4 hbox_fast(const float* __restrict__ rowp, int c) {
    // cols c-4 .. c+7, all in-range, 16B aligned (c % 4 == 0)
    const float4* p = reinterpret_cast<const float4*>(rowp + (c - R));
    float4 a = p[0], b = p[1], d = p[2];
    float h0 = ((a.x + a.y) + (a.z + a.w)) + ((b.x + b.y) + (b.z + b.w)) + d.x;
    float h1 = h0 - a.x + d.y;
    float h2 = h1 - a.y + d.z;
    float h3 = h2 - a.z + d.w;
    return make_float4(h0, h1, h2, h3);
}

__device__ __forceinline__ float4 hbox_slow(const float* __restrict__ rowp, int c, int W) {
    float s[2 * R + CPT];
#pragma unroll
    for (int k = 0; k < 2 * R + CPT; ++k) {
        int cc = c - R + k;
        s[k] = (cc >= 0 && cc < W) ? rowp[cc] : 0.0f;
    }
    float h0 = 0.0f;
#pragma unroll
    for (int k = 0; k < 2 * R + 1; ++k) h0 += s[k];
    float h1 = h0 - s[0] + s[2 * R + 1];
    float h2 = h1 - s[1] + s[2 * R + 2];
    float h3 = h2 - s[2] + s[2 * R + 3];
    return make_float4(h0, h1, h2, h3);
}

__global__ __launch_bounds__(NT, MINB) void box_kernel(
    const float* __restrict__ x, float* __restrict__ out,
    int H, int W, int rows_per_chunk)
{
    const int t = threadIdx.x;
    const int c = blockIdx.x * TW + t * CPT;
    if (c >= W) return;
    const bool fast = (c >= R) && (c + CPT - 1 + R < W);

    const size_t img_off = (size_t)blockIdx.y * (size_t)H * (size_t)W;
    const float* img = x + img_off;
    float* oimg = out + img_off;

    const int y0 = blockIdx.z * rows_per_chunk;
    if (y0 >= H) return;
    const int y1 = min(H, y0 + rows_per_chunk);

    // Prime: vsum = sum of h over rows [max(0, y0-R), y0+R)
    // Invariant entering iteration i: vsum = sum h(rows max(0,i-R) .. i+R-1)
    float4 vsum = make_float4(0.0f, 0.0f, 0.0f, 0.0f);
    if (fast) {
        for (int row = max(0, y0 - R); row < y0 + R && row < H; ++row) {
            float4 h = hbox_fast(img + (size_t)row * W, c);
            vsum.x += h.x; vsum.y += h.y; vsum.z += h.z; vsum.w += h.w;
        }
    } else {
        for (int row = max(0, y0 - R); row < y0 + R && row < H; ++row) {
            float4 h = hbox_slow(img + (size_t)row * W, c, W);
            vsum.x += h.x; vsum.y += h.y; vsum.z += h.z; vsum.w += h.w;
        }
    }

    const int body_lo = min(y1, max(y0, R));           // first i with i-R >= 0
    const int body_hi = max(body_lo, min(y1, H - R));  // last+1 i with i+R < H

    // --- head: i < R, add only (window still growing downward) ---
    for (int i = y0; i < body_lo; ++i) {
        const float* rowp = img + (size_t)(i + R) * W;  // i+R < H here (H >> 2R)
        float4 h = fast ? hbox_fast(rowp, c) : hbox_slow(rowp, c, W);
        vsum.x += h.x; vsum.y += h.y; vsum.z += h.z; vsum.w += h.w;
        *reinterpret_cast<float4*>(oimg + (size_t)i * W + c) = vsum;
    }

    // --- body: interior, branch-free. add row i+R, subtract row i-R (L2-hot) ---
    if (fast) {
        for (int i = body_lo; i < body_hi; ++i) {
            const float* rowp_a = img + (size_t)(i + R) * W;
            const float* rowp_s = img + (size_t)(i - R) * W;
            // issue all 6 LDG.128 up front
            const float4* pa = reinterpret_cast<const float4*>(rowp_a + (c - R));
            const float4* ps = reinterpret_cast<const float4*>(rowp_s + (c - R));
            float4 a0 = pa[0], a1 = pa[1], a2 = pa[2];
            float4 s0 = ps[0], s1 = ps[1], s2 = ps[2];

            float ha0 = ((a0.x + a0.y) + (a0.z + a0.w)) + ((a1.x + a1.y) + (a1.z + a1.w)) + a2.x;
            float ha1 = ha0 - a0.x + a2.y;
            float ha2 = ha1 - a0.y + a2.z;
            float ha3 = ha2 - a0.z + a2.w;

            float hs0 = ((s0.x + s0.y) + (s0.z + s0.w)) + ((s1.x + s1.y) + (s1.z + s1.w)) + s2.x;
            float hs1 = hs0 - s0.x + s2.y;
            float hs2 = hs1 - s0.y + s2.z;
            float hs3 = hs2 - s0.z + s2.w;

            vsum.x += ha0; vsum.y += ha1; vsum.z += ha2; vsum.w += ha3;
            *reinterpret_cast<float4*>(oimg + (size_t)i * W + c) = vsum;
            vsum.x -= hs0; vsum.y -= hs1; vsum.z -= hs2; vsum.w -= hs3;
        }
    } else {
        for (int i = body_lo; i < body_hi; ++i) {
            float4 ha = hbox_slow(img + (size_t)(i + R) * W, c, W);
            float4 hs = hbox_slow(img + (size_t)(i - R) * W, c, W);
            vsum.x += ha.x; vsum.y += ha.y; vsum.z += ha.z; vsum.w += ha.w;
            *reinterpret_cast<float4*>(oimg + (size_t)i * W + c) = vsum;
            vsum.x -= hs.x; vsum.y -= hs.y; vsum.z -= hs.z; vsum.w -= hs.w;
        }
    }

    // --- tail: i + R >= H, subtract only (window shrinking) ---
    for (int i = body_hi; i < y1; ++i) {
        const int ra = i + R;
        if (ra < H) {
            const float* rowp = img + (size_t)ra * W;
            float4 h = fast ? hbox_fast(rowp, c) : hbox_slow(rowp, c, W);
            vsum.x += h.x; vsum.y += h.y; vsum.z += h.z; vsum.w += h.w;
        }
        *reinterpret_cast<float4*>(oimg + (size_t)i * W + c) = vsum;
        if (i - R >= 0) {
            const float* rowp = img + (size_t)(i - R) * W;
            float4 h = fast ? hbox_fast(rowp, c) : hbox_slow(rowp, c, W);
            vsum.x -= h.x; vsum.y -= h.y; vsum.z -= h.z; vsum.w -= h.w;
        }
    }
}

extern "C" void kernel_launch(void* const* d_in, const int* in_sizes, int n_in,
                              void* d_out, int out_size) {
    const float* x = (const float*)d_in[0];
    float* out = (float*)d_out;

    const int H = 1080;
    const int W = 1920;
    const int BC = out_size / (H * W);   // 24 (B*C)

    const int rows_per_chunk = (H + ZCHUNKS - 1) / ZCHUNKS;  // 45
    dim3 grid((W + TW - 1) / TW, BC, ZCHUNKS);               // 3 x 24 x 24 = 1728 blocks
    box_kernel<<<grid, NT>>>(x, out, H, W, rows_per_chunk);
}

// round 9
// speedup vs baseline: 1.3002x; 1.1851x over previous
#include <cuda_runtime.h>
#include <cuda_bf16.h>

// BoxFilter: out[b,c,i,j] = sum of x over rows [max(0,i-R), min(H-1,i+R)]
//                                        cols [max(0,j-R), min(W-1,j+R)]
// (identity of diff_y(cumsum(diff_x(cumsum(x,H),r),W),r) with truncated edges)
//
// Single pass. Horizontal 9-tap via 3 aligned LDG.128 + sliding window.
// Vertical running sum with a per-thread smem ring (depth 8; 2R==8 so the
// subtract slot equals the add slot -> read-before-write, no ring pointer).
// Each thread touches only ring[*][t]: NO __syncthreads anywhere.

#define R 4
#define NT 160                 // threads per block (5 warps)
#define MINB 8                 // 8 blocks/SM -> regs capped at 51, 40 warps/SM
#define CPT 4                  // columns per thread (float4)
#define TW (NT * CPT)          // 640 cols per block tile -> 1920/640 = 3 exact
#define ZCHUNKS 16             // 3*24*16 = 1152 blocks <= 148*8 -> single wave
#define RING 8                 // == 2R

__device__ __forceinline__ float4 hbox_fast(const float* __restrict__ rowp, int c) {
    // cols c-4 .. c+7, all in-range, 16B aligned (c % 4 == 0)
    const float4* p = reinterpret_cast<const float4*>(rowp + (c - R));
    float4 a = p[0], b = p[1], d = p[2];
    float h0 = ((a.x + a.y) + (a.z + a.w)) + ((b.x + b.y) + (b.z + b.w)) + d.x;
    float h1 = h0 - a.x + d.y;
    float h2 = h1 - a.y + d.z;
    float h3 = h2 - a.z + d.w;
    return make_float4(h0, h1, h2, h3);
}

__device__ __forceinline__ float4 hbox_slow(const float* __restrict__ rowp, int c, int W) {
    float s[2 * R + CPT];
#pragma unroll
    for (int k = 0; k < 2 * R + CPT; ++k) {
        int cc = c - R + k;
        s[k] = (cc >= 0 && cc < W) ? rowp[cc] : 0.0f;
    }
    float h0 = 0.0f;
#pragma unroll
    for (int k = 0; k < 2 * R + 1; ++k) h0 += s[k];
    float h1 = h0 - s[0] + s[2 * R + 1];
    float h2 = h1 - s[1] + s[2 * R + 2];
    float h3 = h2 - s[2] + s[2 * R + 3];
    return make_float4(h0, h1, h2, h3);
}

__global__ __launch_bounds__(NT, MINB) void box_kernel(
    const float* __restrict__ x, float* __restrict__ out,
    int H, int W, int rows_per_chunk)
{
    __shared__ float4 ring[RING][NT];   // 20.5 KB; per-thread private slots

    const int t = threadIdx.x;
    const int c = blockIdx.x * TW + t * CPT;
    if (c >= W) return;
    const bool fast = (c >= R) && (c + CPT - 1 + R < W);

    const size_t img_off = (size_t)blockIdx.y * (size_t)H * (size_t)W;
    const float* img = x + img_off;
    float* oimg = out + img_off;

    const int y0 = blockIdx.z * rows_per_chunk;
    if (y0 >= H) return;
    const int y1 = min(H, y0 + rows_per_chunk);

    // Prime: vsum = sum h(rows max(0,y0-R) .. y0+R-1); stash each h in the ring.
    // Invariant entering iteration i: vsum = sum h(max(0,i-R) .. i+R-1),
    // ring holds h for the last up-to-8 rows processed.
    float4 vsum = make_float4(0.0f, 0.0f, 0.0f, 0.0f);
    for (int row = max(0, y0 - R); row < y0 + R && row < H; ++row) {
        const float* rowp = img + (size_t)row * W;
        float4 h = fast ? hbox_fast(rowp, c) : hbox_slow(rowp, c, W);
        ring[row & (RING - 1)][t] = h;
        vsum.x += h.x; vsum.y += h.y; vsum.z += h.z; vsum.w += h.w;
    }

    const int body_lo = min(y1, max(y0, R));           // first i with i-R >= 0
    const int body_hi = max(body_lo, min(y1, H - R));  // last+1 i with i+R < H

    // --- head: i < R, add only (window still growing downward) ---
    for (int i = y0; i < body_lo; ++i) {
        const int ra = i + R;                           // < H (H >> 2R)
        const float* rowp = img + (size_t)ra * W;
        float4 h = fast ? hbox_fast(rowp, c) : hbox_slow(rowp, c, W);
        ring[ra & (RING - 1)][t] = h;
        vsum.x += h.x; vsum.y += h.y; vsum.z += h.z; vsum.w += h.w;
        *reinterpret_cast<float4*>(oimg + (size_t)i * W + c) = vsum;
    }

    // --- body: interior, branch-free. slot(i+R) == slot(i-R) since 2R == RING.
    if (fast) {
        for (int i = body_lo; i < body_hi; ++i) {
            const int slot = (i + R) & (RING - 1);
            float4 g = ring[slot][t];                   // h(i-R), read before write
            const float4* pa = reinterpret_cast<const float4*>(
                img + (size_t)(i + R) * W + (c - R));
            float4 a0 = pa[0], a1 = pa[1], a2 = pa[2];

            float h0 = ((a0.x + a0.y) + (a0.z + a0.w)) + ((a1.x + a1.y) + (a1.z + a1.w)) + a2.x;
            float h1 = h0 - a0.x + a2.y;
            float h2 = h1 - a0.y + a2.z;
            float h3 = h2 - a0.z + a2.w;

            ring[slot][t] = make_float4(h0, h1, h2, h3);
            vsum.x += h0; vsum.y += h1; vsum.z += h2; vsum.w += h3;
            *reinterpret_cast<float4*>(oimg + (size_t)i * W + c) = vsum;
            vsum.x -= g.x; vsum.y -= g.y; vsum.z -= g.z; vsum.w -= g.w;
        }
    } else {
        for (int i = body_lo; i < body_hi; ++i) {
            const int slot = (i + R) & (RING - 1);
            float4 g = ring[slot][t];
            float4 h = hbox_slow(img + (size_t)(i + R) * W, c, W);
            ring[slot][t] = h;
            vsum.x += h.x; vsum.y += h.y; vsum.z += h.z; vsum.w += h.w;
            *reinterpret_cast<float4*>(oimg + (size_t)i * W + c) = vsum;
            vsum.x -= g.x; vsum.y -= g.y; vsum.z -= g.z; vsum.w -= g.w;
        }
    }

    // --- tail: i + R >= H, subtract only (window shrinking) ---
    for (int i = body_hi; i < y1; ++i) {
        const int ra = i + R;
        if (ra < H) {
            const float* rowp = img + (size_t)ra * W;
            float4 h = fast ? hbox_fast(rowp, c) : hbox_slow(rowp, c, W);
            ring[ra & (RING - 1)][t] = h;
            vsum.x += h.x; vsum.y += h.y; vsum.z += h.z; vsum.w += h.w;
        }
        *reinterpret_cast<float4*>(oimg + (size_t)i * W + c) = vsum;
        if (i - R >= 0) {
            float4 g = ring[(i - R) & (RING - 1)][t];
            vsum.x -= g.x; vsum.y -= g.y; vsum.z -= g.z; vsum.w -= g.w;
        }
    }
}

extern "C" void kernel_launch(void* const* d_in, const int* in_sizes, int n_in,
                              void* d_out, int out_size) {
    const float* x = (const float*)d_in[0];
    float* out = (float*)d_out;

    const int H = 1080;
    const int W = 1920;
    const int BC = out_size / (H * W);   // 24 (B*C)

    const int rows_per_chunk = (H + ZCHUNKS - 1) / ZCHUNKS;  // 68
    dim3 grid((W + TW - 1) / TW, BC, ZCHUNKS);               // 3 x 24 x 16 = 1152 blocks
    box_kernel<<<grid, NT>>>(x, out, H, W, rows_per_chunk);
}